// round 16
// baseline (speedup 1.0000x reference)
#include <cuda_runtime.h>

#define NS 4096
#define GRID_ALL 272
typedef unsigned long long u64;

// f32x2 packed math (sm_103a): one FFMA2 = 2 fp32 FMAs
#define PACKDUP(d, x)  asm("mov.b64 %0, {%1, %1};" : "=l"(d) : "f"(x))
#define FFMA2(d, a, b) asm("fma.rn.f32x2 %0, %1, %2, %0;" : "+l"(d) : "l"(a), "l"(b))
#define UNPACK64(lo, hi, v) asm("mov.b64 {%0, %1}, %2;" : "=f"(lo), "=f"(hi) : "l"(v))

// ---- scratch (device globals: no allocation allowed) ----
__device__ float g_P[512 * 256];     // prefix table  (c0,c1,c2)
__device__ float g_S[512 * 256];     // suffix table  (c5,c6,c7)
__device__ float g_V1[NS * 256];     // intermediate after level-3 GEMM
__device__ int   g_p[NS];
__device__ int   g_q[NS];
__device__ int   g_cnt3[8];          // zero-init at load; tickets re-zero each run
__device__ int   g_cnt4[8];
__device__ int   g_b3[8 * NS];
__device__ int   g_b4[8 * NS];
__device__ int   g_done3;
__device__ int   g_done4;
__device__ int   g_bar_count;        // grid barrier state
__device__ int   g_bar_gen;          // generation: monotonically increasing

// ---------------------------------------------------------------------------
// Grid-wide barrier. Safe because GRID_ALL=272 blocks (128 thr, 64KB smem,
// 3 blocks/SM -> 444 slots on 148 SMs) are all resident in wave 1.
__device__ __forceinline__ void grid_barrier() {
    __threadfence();            // release: all prior writes visible at L2
    __syncthreads();
    if (threadIdx.x == 0) {
        int gen = *(volatile int*)&g_bar_gen;
        if (atomicAdd(&g_bar_count, 1) == GRID_ALL - 1) {
            g_bar_count = 0;
            __threadfence();
            *(volatile int*)&g_bar_gen = gen + 1;
        } else {
            while (*(volatile int*)&g_bar_gen == gen) __nanosleep(64);
        }
    }
    __syncthreads();
}

// map flat tile id -> (bucket, base); computed redundantly in all threads
__device__ __forceinline__ int2 tile_map(const int* __restrict__ cnt, int t) {
    int acc = 0, c = -1, base = 0;
#pragma unroll
    for (int i = 0; i < 8; i++) {
        int tiles = (cnt[i] + 31) >> 5;
        if (c < 0 && t < acc + tiles) { c = i; base = (t - acc) * 32; }
        acc += tiles;
    }
    return make_int2(c, base);
}

#define TICKET_CLEAN(DONE, CNT)                                                \
    {                                                                          \
        __syncthreads();                                                       \
        if (tid == 0) {                                                        \
            int old = atomicAdd(&DONE, 1);                                     \
            if (old == GRID_ALL - 1) {                                         \
                _Pragma("unroll")                                              \
                for (int j = 0; j < 8; j++) CNT[j] = 0;                        \
                DONE = 0;                                                      \
            }                                                                  \
        }                                                                      \
    }

// ---- GEMM building blocks (identical math to the 52us kernel) ----
#define LDB(KC)                                                                \
    {                                                                          \
        _Pragma("unroll")                                                      \
        for (int p4 = 0; p4 < 8; p4++)                                         \
            nb[p4] = __ldg((const float4*)(Bg + ((KC) * 32 + p4 * 4 + brow) * 2048 + bcol)); \
    }
#define STB(BUF)                                                               \
    {                                                                          \
        _Pragma("unroll")                                                      \
        for (int p4 = 0; p4 < 8; p4++)                                         \
            *(float4*)&Bs[(BUF) * 4096 + (p4 * 4 + brow) * 128 + bcol] = nb[p4]; \
    }
#define CHUNK_COMPUTE(KC, BUF)                                                 \
    {                                                                          \
        _Pragma("unroll 8")                                                    \
        for (int kk = 0; kk < 32; kk++) {                                      \
            float4 b = *(const float4*)&Bs[(BUF) * 4096 + kk * 128 + colg * 4]; \
            u64 bd0, bd1, bd2, bd3;                                            \
            PACKDUP(bd0, b.x); PACKDUP(bd1, b.y);                              \
            PACKDUP(bd2, b.z); PACKDUP(bd3, b.w);                              \
            const u64* ap = (const u64*)&Ast[((KC) * 32 + kk) * 32 + sg * 8];  \
            u64 a0 = ap[0], a1 = ap[1], a2 = ap[2], a3 = ap[3];                \
            FFMA2(acc[0][0], a0, bd0); FFMA2(acc[0][1], a0, bd1);              \
            FFMA2(acc[0][2], a0, bd2); FFMA2(acc[0][3], a0, bd3);              \
            FFMA2(acc[1][0], a1, bd0); FFMA2(acc[1][1], a1, bd1);              \
            FFMA2(acc[1][2], a1, bd2); FFMA2(acc[1][3], a1, bd3);              \
            FFMA2(acc[2][0], a2, bd0); FFMA2(acc[2][1], a2, bd1);              \
            FFMA2(acc[2][2], a2, bd2); FFMA2(acc[2][3], a2, bd3);              \
            FFMA2(acc[3][0], a3, bd0); FFMA2(acc[3][1], a3, bd1);              \
            FFMA2(acc[3][2], a3, bd2); FFMA2(acc[3][3], a3, bd3);              \
        }                                                                      \
    }
#define GEMM_MAIN()                                                            \
    LDB(0); STB(0); __syncthreads();                                           \
    _Pragma("unroll 1")                                                        \
    for (int kc = 0; kc < 8; kc++) {                                           \
        if (kc < 7) LDB(kc + 1);                                               \
        CHUNK_COMPUTE(kc, kc & 1);                                             \
        if (kc < 7) { STB((kc + 1) & 1); __syncthreads(); }                    \
    }
#define STAGE_A(SRC, ROWSEL)                                                   \
    {                                                                          \
        int s = tid & 31;                                                      \
        int li = base + s;                                                     \
        int rsel = -1;                                                         \
        if (li < cnt) { int nn = ROWSEL; rsel = nn; }                          \
        _Pragma("unroll")                                                      \
        for (int pass = 0; pass < 16; pass++) {                                \
            int kq = (tid >> 5) + 4 * pass;                                    \
            float4 v = make_float4(0.f, 0.f, 0.f, 0.f);                        \
            if (rsel >= 0) v = __ldg((const float4*)(SRC + rsel * 256 + kq * 4)); \
            Ast[(kq * 4 + 0) * 32 + s] = v.x;                                  \
            Ast[(kq * 4 + 1) * 32 + s] = v.y;                                  \
            Ast[(kq * 4 + 2) * 32 + s] = v.z;                                  \
            Ast[(kq * 4 + 3) * 32 + s] = v.w;                                  \
        }                                                                      \
    }

// ---------------------------------------------------------------------------
// ONE persistent kernel: phase0 (tables + decode) | barrier | gemm3 | barrier
// | gemm4 + suffix dot. Dynamic smem: Ast 8192 floats + Bs 8192 floats = 64KB.
__global__ void __launch_bounds__(128, 3) k_all(
    const float* __restrict__ c0, const float* __restrict__ c1,
    const float* __restrict__ c2, const float* __restrict__ B3,
    const float* __restrict__ B4, const float* __restrict__ c5,
    const float* __restrict__ c6, const float* __restrict__ c7,
    const int*   __restrict__ coords, float* __restrict__ out)
{
    extern __shared__ float smem[];
    float* Ast = smem;           // 8192 floats
    float* Bs  = smem + 8192;    // 8192 floats
    int tid = threadIdx.x;
    int bx = blockIdx.x;

    // ================= PHASE 0 =================
    if (bx < 32) {
        // ---- prefix: P[(ab,c)][col] = T[ab] @ core2[:,c,col] ----
        __shared__ float sc0[64];
        float* sA = Ast;   // [r*68+ab]
        float* sB = Bs;    // staging + [r*68+cc]
        int cdig = bx >> 2, col0 = (bx & 3) * 64;
        if (tid < 64) sc0[tid] = c0[tid];
        for (int e = tid; e < 4096; e += 128) sB[e] = c1[e];
        __syncthreads();
        for (int e = tid; e < 4096; e += 128) {
            int r = e >> 6, ab = e & 63;
            int a = ab >> 3, b = ab & 7;
            float acc = 0.f;
#pragma unroll
            for (int i = 0; i < 8; i++)
                acc += sc0[a * 8 + i] * sB[(i * 8 + b) * 64 + r];
            sA[r * 68 + ab] = acc;
        }
        __syncthreads();
        for (int e = tid; e < 4096; e += 128) {
            int r = e >> 6, cc = e & 63;
            sB[r * 68 + cc] = c2[(r * 8 + cdig) * 256 + col0 + cc];
        }
        __syncthreads();
        int ct = tid & 15, abt = tid >> 4;          // 16 col-quads x 8 ab-octets
        float acc[8][4] = {};
        for (int r = 0; r < 64; r++) {
            float4 bv = *(const float4*)&sB[r * 68 + ct * 4];
#pragma unroll
            for (int ii = 0; ii < 8; ii++) {
                float av = sA[r * 68 + abt * 8 + ii];
                acc[ii][0] += av * bv.x; acc[ii][1] += av * bv.y;
                acc[ii][2] += av * bv.z; acc[ii][3] += av * bv.w;
            }
        }
#pragma unroll
        for (int ii = 0; ii < 8; ii++) {
            int p = (abt * 8 + ii) * 8 + cdig;
            *(float4*)&g_P[p * 256 + col0 + ct * 4] =
                make_float4(acc[ii][0], acc[ii][1], acc[ii][2], acc[ii][3]);
        }
    } else if (bx < 64) {
        // ---- suffix: S[(a,bc)][row] = core5[row,a,:64] @ U[bc] ----
        __shared__ float sc7[64];
        float* sA = Ast;
        float* sB = Bs;
        int b2 = bx - 32;
        int adig = b2 >> 2, row0 = (b2 & 3) * 64;
        if (tid < 64) sc7[tid] = c7[tid];
        for (int e = tid; e < 4096; e += 128) sA[e] = c6[e];
        __syncthreads();
        for (int e = tid; e < 4096; e += 128) {
            int j = e >> 6, bc = e & 63;
            int b = bc >> 3, cd = bc & 7;
            float acc = 0.f;
#pragma unroll
            for (int i = 0; i < 8; i++)
                acc += sA[(j * 8 + b) * 8 + i] * sc7[i * 8 + cd];
            sB[j * 68 + bc] = acc;
        }
        __syncthreads();
        for (int e = tid; e < 4096; e += 128) {
            int r = e >> 6, j = e & 63;
            sA[j * 68 + r] = c5[((row0 + r) * 8 + adig) * 64 + j];
        }
        __syncthreads();
        int rt = tid & 15, bct = tid >> 4;
        float acc[8][4] = {};
        for (int j = 0; j < 64; j++) {
            float4 av = *(const float4*)&sA[j * 68 + rt * 4];
#pragma unroll
            for (int jj = 0; jj < 8; jj++) {
                float uv = sB[j * 68 + bct * 8 + jj];
                acc[jj][0] += av.x * uv; acc[jj][1] += av.y * uv;
                acc[jj][2] += av.z * uv; acc[jj][3] += av.w * uv;
            }
        }
#pragma unroll
        for (int jj = 0; jj < 8; jj++) {
            int q = adig * 64 + bct * 8 + jj;
            *(float4*)&g_S[q * 256 + row0 + rt * 4] =
                make_float4(acc[jj][0], acc[jj][1], acc[jj][2], acc[jj][3]);
        }
    } else if (bx < 96) {
        // ---- decode + zero out; smem histogram -> 8 global atomics/block ----
        __shared__ int h3[8], h4[8], base3[8], base4[8];
        int n = (bx - 64) * 128 + tid;
        if (tid < 8) { h3[tid] = 0; h4[tid] = 0; }
        __syncthreads();
        out[n] = 0.f;   // gemm4 halves accumulate via atomicAdd
        int x = coords[3 * n], y = coords[3 * n + 1], z = coords[3 * n + 2];
        int d[8];
#pragma unroll
        for (int l = 0; l < 8; l++) {
            int sh = 7 - l;
            d[l] = 4 * ((x >> sh) & 1) + 2 * ((y >> sh) & 1) + ((z >> sh) & 1);
        }
        g_p[n] = d[0] * 64 + d[1] * 8 + d[2];
        g_q[n] = d[5] * 64 + d[6] * 8 + d[7];
        int d3 = d[3], d4 = d[4];
        int l3 = atomicAdd(&h3[d3], 1);
        int l4 = atomicAdd(&h4[d4], 1);
        __syncthreads();
        if (tid < 8)       base3[tid] = atomicAdd(&g_cnt3[tid], h3[tid]);
        else if (tid < 16) base4[tid - 8] = atomicAdd(&g_cnt4[tid - 8], h4[tid - 8]);
        __syncthreads();
        g_b3[d3 * NS + base3[d3] + l3] = n;
        g_b4[d4 * NS + base4[d4] + l4] = n;
    }

    grid_barrier();

    // ================= PHASE 1: level-3 GEMM =================
    {
        int t = bx >> 1, half = bx & 1;
        int2 cb = tile_map(g_cnt3, t);
        int c = cb.x, base = cb.y;
        int cnt = (c >= 0) ? g_cnt3[c] : 0;
        TICKET_CLEAN(g_done3, g_cnt3);
        if (c >= 0) {
            STAGE_A(g_P, g_p[g_b3[c * NS + li]]);
            __syncthreads();
            int colg = tid & 31, sg = tid >> 5;
            int brow = tid >> 5, bcol = (tid & 31) * 4;
            const float* Bg = B3 + c * 256 + half * 128;
            float4 nb[8];
            u64 acc[4][4] = {};
            GEMM_MAIN();
#pragma unroll
            for (int p = 0; p < 4; p++) {
                float lo0, lo1, lo2, lo3, hi0, hi1, hi2, hi3;
                UNPACK64(lo0, hi0, acc[p][0]); UNPACK64(lo1, hi1, acc[p][1]);
                UNPACK64(lo2, hi2, acc[p][2]); UNPACK64(lo3, hi3, acc[p][3]);
                int l0 = base + sg * 8 + 2 * p, l1 = l0 + 1;
                int n0 = (l0 < cnt) ? g_b3[c * NS + l0] : -1;
                int n1 = (l1 < cnt) ? g_b3[c * NS + l1] : -1;
                if (n0 >= 0) *(float4*)&g_V1[n0 * 256 + half * 128 + colg * 4] =
                    make_float4(lo0, lo1, lo2, lo3);
                if (n1 >= 0) *(float4*)&g_V1[n1 * 256 + half * 128 + colg * 4] =
                    make_float4(hi0, hi1, hi2, hi3);
            }
        }
    }

    grid_barrier();

    // ================= PHASE 2: level-4 GEMM + suffix dot =================
    {
        int t = bx >> 1, half = bx & 1;
        int2 cb = tile_map(g_cnt4, t);
        int c = cb.x, base = cb.y;
        int cnt = (c >= 0) ? g_cnt4[c] : 0;
        TICKET_CLEAN(g_done4, g_cnt4);
        if (c >= 0) {
            STAGE_A(g_V1, g_b4[c * NS + li]);
            __syncthreads();
            int colg = tid & 31, sg = tid >> 5;
            int brow = tid >> 5, bcol = (tid & 31) * 4;
            const float* Bg = B4 + c * 256 + half * 128;
            float4 nb[8];
            u64 acc[4][4] = {};
            GEMM_MAIN();

            float part[8];
#pragma unroll
            for (int p = 0; p < 4; p++) {
                float lo0, lo1, lo2, lo3, hi0, hi1, hi2, hi3;
                UNPACK64(lo0, hi0, acc[p][0]); UNPACK64(lo1, hi1, acc[p][1]);
                UNPACK64(lo2, hi2, acc[p][2]); UNPACK64(lo3, hi3, acc[p][3]);
                int l0 = base + sg * 8 + 2 * p, l1 = l0 + 1;
                int nn0 = (l0 < cnt) ? g_b4[c * NS + l0] : -1;
                int nn1 = (l1 < cnt) ? g_b4[c * NS + l1] : -1;
                int q0 = (nn0 >= 0) ? g_q[nn0] : 0;
                int q1 = (nn1 >= 0) ? g_q[nn1] : 0;
                float4 s0 = *(const float4*)(g_S + q0 * 256 + half * 128 + colg * 4);
                float4 s1 = *(const float4*)(g_S + q1 * 256 + half * 128 + colg * 4);
                part[2 * p]     = lo0 * s0.x + lo1 * s0.y + lo2 * s0.z + lo3 * s0.w;
                part[2 * p + 1] = hi0 * s1.x + hi1 * s1.y + hi2 * s1.z + hi3 * s1.w;
            }
#pragma unroll
            for (int i = 0; i < 8; i++) {
#pragma unroll
                for (int off = 16; off > 0; off >>= 1)
                    part[i] += __shfl_xor_sync(0xffffffffu, part[i], off);
            }
            if (colg == 0) {
                // two halves accumulate; a+b == b+a bitwise -> deterministic
#pragma unroll
                for (int i = 0; i < 8; i++) {
                    int l = base + sg * 8 + i;
                    if (l < cnt) atomicAdd(out + g_b4[c * NS + l], part[i]);
                }
            }
        }
    }
}

// ---------------------------------------------------------------------------
extern "C" void kernel_launch(void* const* d_in, const int* in_sizes, int n_in,
                              void* d_out, int out_size) {
    const float* core0 = (const float*)d_in[0];
    const float* core1 = (const float*)d_in[1];
    const float* core2 = (const float*)d_in[2];
    const float* core3 = (const float*)d_in[3];
    const float* core4 = (const float*)d_in[4];
    const float* core5 = (const float*)d_in[5];
    const float* core6 = (const float*)d_in[6];
    const float* core7 = (const float*)d_in[7];
    const int*   coords = (const int*)d_in[8];
    float* out = (float*)d_out;

    const int smem_bytes = 2 * 8192 * 4;   // 64KB dynamic
    static bool attr_set = false;
    if (!attr_set) {
        cudaFuncSetAttribute(k_all, cudaFuncAttributeMaxDynamicSharedMemorySize,
                             smem_bytes);
        attr_set = true;
    }

    k_all<<<GRID_ALL, 128, smem_bytes>>>(core0, core1, core2, core3, core4,
                                         core5, core6, core7, coords, out);
}

// round 17
// speedup vs baseline: 1.0792x; 1.0792x over previous
#include <cuda_runtime.h>

#define NS 4096
typedef unsigned long long u64;

// f32x2 packed math (sm_103a): one FFMA2 = 2 fp32 FMAs
#define PACKDUP(d, x)  asm("mov.b64 %0, {%1, %1};" : "=l"(d) : "f"(x))
#define FFMA2(d, a, b) asm("fma.rn.f32x2 %0, %1, %2, %0;" : "+l"(d) : "l"(a), "l"(b))
#define UNPACK64(lo, hi, v) asm("mov.b64 {%0, %1}, %2;" : "=f"(lo), "=f"(hi) : "l"(v))

// ---- scratch (device globals: no allocation allowed) ----
__device__ float g_P[512 * 256];     // prefix table  (c0,c1,c2)
__device__ float g_S[512 * 256];     // suffix table  (c5,c6,c7)
__device__ float g_V1[NS * 256];     // intermediate after level-3 GEMM
__device__ int   g_p[NS];
__device__ int   g_q[NS];
__device__ int   g_cnt3[8];          // zero-init at load; tickets re-zero each run
__device__ int   g_cnt4[8];
__device__ int   g_b3[8 * NS];
__device__ int   g_b4[8 * NS];
__device__ int   g_done3;
__device__ int   g_done4;

#define GRID3 272
#define GRID4 272

// ---------------------------------------------------------------------------
// Setup, 144 blocks x 256 thr:
//   blocks 0-63   : prefix table, 32-col slices  (cdig = b>>3, col0 = (b&7)*32)
//   blocks 64-127 : suffix table, 32-row slices  (adig = ..., row0 = ...)
//   blocks 128-143: decode + smem-histogram bucketing + zero out
__global__ void __launch_bounds__(256) k_setup(
    const float* __restrict__ c0, const float* __restrict__ c1,
    const float* __restrict__ c2, const float* __restrict__ c5,
    const float* __restrict__ c6, const float* __restrict__ c7,
    const int*   __restrict__ coords, float* __restrict__ out)
{
    int bid = blockIdx.x;
    int tid = threadIdx.x;

    if (bid < 64) {
        // ---- prefix: P[(ab,c)][col0..col0+31] = T[ab] @ core2[:,c,cols] ----
        __shared__ float sA[64 * 68];   // T[r][ab]
        __shared__ float sB[64 * 68];   // c1 staging, then c2 tile [r][cc] pad 36
        __shared__ float sc0[64];
        int cdig = bid >> 3, col0 = (bid & 7) * 32;
        if (tid < 64) sc0[tid] = c0[tid];
        for (int e = tid; e < 4096; e += 256) sB[e] = __ldg(c1 + e);
        __syncthreads();
        for (int e = tid; e < 4096; e += 256) {
            int r = e >> 6, ab = e & 63;
            int a = ab >> 3, b = ab & 7;
            float acc = 0.f;
#pragma unroll
            for (int i = 0; i < 8; i++)
                acc += sc0[a * 8 + i] * sB[(i * 8 + b) * 64 + r];
            sA[r * 68 + ab] = acc;
        }
        __syncthreads();
        for (int e = tid; e < 2048; e += 256) {
            int r = e >> 5, cc = e & 31;
            sB[r * 36 + cc] = __ldg(c2 + (r * 8 + cdig) * 256 + col0 + cc);
        }
        __syncthreads();
        int ct = tid & 7, abt = tid >> 3;        // 8 col-quads x 32 ab-pairs
        float acc[2][4] = {};
        for (int r = 0; r < 64; r++) {
            float4 bv = *(const float4*)&sB[r * 36 + ct * 4];
            float a0 = sA[r * 68 + abt * 2], a1 = sA[r * 68 + abt * 2 + 1];
            acc[0][0] += a0 * bv.x; acc[0][1] += a0 * bv.y;
            acc[0][2] += a0 * bv.z; acc[0][3] += a0 * bv.w;
            acc[1][0] += a1 * bv.x; acc[1][1] += a1 * bv.y;
            acc[1][2] += a1 * bv.z; acc[1][3] += a1 * bv.w;
        }
#pragma unroll
        for (int ii = 0; ii < 2; ii++) {
            int p = (abt * 2 + ii) * 8 + cdig;
            *(float4*)&g_P[p * 256 + col0 + ct * 4] =
                make_float4(acc[ii][0], acc[ii][1], acc[ii][2], acc[ii][3]);
        }
    } else if (bid < 128) {
        // ---- suffix: S[(a,bc)][row0..row0+31] = core5[rows,a,:64] @ U[bc] ----
        __shared__ float sA[64 * 68];   // c6 staging, then c5T [j][r] pad 36
        __shared__ float sB[64 * 68];   // U[j][bc]
        __shared__ float sc7[64];
        int b2 = bid - 64;
        int adig = b2 >> 3, row0 = (b2 & 7) * 32;
        if (tid < 64) sc7[tid] = c7[tid];
        for (int e = tid; e < 4096; e += 256) sA[e] = __ldg(c6 + e);
        __syncthreads();
        for (int e = tid; e < 4096; e += 256) {
            int j = e >> 6, bc = e & 63;
            int b = bc >> 3, cd = bc & 7;
            float acc = 0.f;
#pragma unroll
            for (int i = 0; i < 8; i++)
                acc += sA[(j * 8 + b) * 8 + i] * sc7[i * 8 + cd];
            sB[j * 68 + bc] = acc;
        }
        __syncthreads();
        for (int e = tid; e < 2048; e += 256) {
            int r = e >> 6, j = e & 63;          // 32 rows x 64 j, coalesced in j
            sA[j * 36 + r] = __ldg(c5 + ((row0 + r) * 8 + adig) * 64 + j);
        }
        __syncthreads();
        int rt = tid & 7, bct = tid >> 3;        // 8 row-quads x 32 bc-pairs
        float acc[2][4] = {};
        for (int j = 0; j < 64; j++) {
            float4 av = *(const float4*)&sA[j * 36 + rt * 4];
            float u0 = sB[j * 68 + bct * 2], u1 = sB[j * 68 + bct * 2 + 1];
            acc[0][0] += av.x * u0; acc[0][1] += av.y * u0;
            acc[0][2] += av.z * u0; acc[0][3] += av.w * u0;
            acc[1][0] += av.x * u1; acc[1][1] += av.y * u1;
            acc[1][2] += av.z * u1; acc[1][3] += av.w * u1;
        }
#pragma unroll
        for (int jj = 0; jj < 2; jj++) {
            int q = adig * 64 + bct * 2 + jj;
            *(float4*)&g_S[q * 256 + row0 + rt * 4] =
                make_float4(acc[jj][0], acc[jj][1], acc[jj][2], acc[jj][3]);
        }
    } else {
        // ---- decode + zero out; smem histogram -> 8 global atomics/block ----
        __shared__ int h3[8], h4[8], base3[8], base4[8];
        int n = (bid - 128) * 256 + tid;
        if (tid < 8) { h3[tid] = 0; h4[tid] = 0; }
        __syncthreads();
        out[n] = 0.f;   // gemm4 halves accumulate via atomicAdd
        int x = coords[3 * n], y = coords[3 * n + 1], z = coords[3 * n + 2];
        int d[8];
#pragma unroll
        for (int l = 0; l < 8; l++) {
            int sh = 7 - l;
            d[l] = 4 * ((x >> sh) & 1) + 2 * ((y >> sh) & 1) + ((z >> sh) & 1);
        }
        g_p[n] = d[0] * 64 + d[1] * 8 + d[2];
        g_q[n] = d[5] * 64 + d[6] * 8 + d[7];
        int d3 = d[3], d4 = d[4];
        int l3 = atomicAdd(&h3[d3], 1);
        int l4 = atomicAdd(&h4[d4], 1);
        __syncthreads();
        if (tid < 8)       base3[tid] = atomicAdd(&g_cnt3[tid], h3[tid]);
        else if (tid < 16) base4[tid - 8] = atomicAdd(&g_cnt4[tid - 8], h4[tid - 8]);
        __syncthreads();
        g_b3[d3 * NS + base3[d3] + l3] = n;
        g_b4[d4 * NS + base4[d4] + l4] = n;
    }
}

// ---------------------------------------------------------------------------
// Pipelined FFMA2 GEMM (identical to the 52.0us kernel): 32 samples x 128
// cols, K=256, 128 threads, double-buffered Bs, one barrier per K-chunk.
// Shared = Ast[256][32] 32KB + Bs[2][32][128] 32KB = 64KB.

__device__ __forceinline__ int2 tile_map(const int* __restrict__ cnt, int t) {
    int acc = 0, c = -1, base = 0;
#pragma unroll
    for (int i = 0; i < 8; i++) {
        int tiles = (cnt[i] + 31) >> 5;
        if (c < 0 && t < acc + tiles) { c = i; base = (t - acc) * 32; }
        acc += tiles;
    }
    return make_int2(c, base);
}

#define TICKET_CLEAN(DONE, CNT, TOTAL)                                         \
    {                                                                          \
        __syncthreads();                                                       \
        if (tid == 0) {                                                        \
            int old = atomicAdd(&DONE, 1);                                     \
            if (old == (TOTAL) - 1) {                                          \
                _Pragma("unroll")                                              \
                for (int j = 0; j < 8; j++) CNT[j] = 0;                        \
                DONE = 0;                                                      \
            }                                                                  \
        }                                                                      \
    }

#define LDB(KC)                                                                \
    {                                                                          \
        _Pragma("unroll")                                                      \
        for (int p4 = 0; p4 < 8; p4++)                                         \
            nb[p4] = __ldg((const float4*)(Bg + ((KC) * 32 + p4 * 4 + brow) * 2048 + bcol)); \
    }
#define STB(BUF)                                                               \
    {                                                                          \
        _Pragma("unroll")                                                      \
        for (int p4 = 0; p4 < 8; p4++)                                         \
            *(float4*)&Bs[(BUF) * 4096 + (p4 * 4 + brow) * 128 + bcol] = nb[p4]; \
    }
#define CHUNK_COMPUTE(KC, BUF)                                                 \
    {                                                                          \
        _Pragma("unroll 8")                                                    \
        for (int kk = 0; kk < 32; kk++) {                                      \
            float4 b = *(const float4*)&Bs[(BUF) * 4096 + kk * 128 + colg * 4]; \
            u64 bd0, bd1, bd2, bd3;                                            \
            PACKDUP(bd0, b.x); PACKDUP(bd1, b.y);                              \
            PACKDUP(bd2, b.z); PACKDUP(bd3, b.w);                              \
            const u64* ap = (const u64*)&Ast[((KC) * 32 + kk) * 32 + sg * 8];  \
            u64 a0 = ap[0], a1 = ap[1], a2 = ap[2], a3 = ap[3];                \
            FFMA2(acc[0][0], a0, bd0); FFMA2(acc[0][1], a0, bd1);              \
            FFMA2(acc[0][2], a0, bd2); FFMA2(acc[0][3], a0, bd3);              \
            FFMA2(acc[1][0], a1, bd0); FFMA2(acc[1][1], a1, bd1);              \
            FFMA2(acc[1][2], a1, bd2); FFMA2(acc[1][3], a1, bd3);              \
            FFMA2(acc[2][0], a2, bd0); FFMA2(acc[2][1], a2, bd1);              \
            FFMA2(acc[2][2], a2, bd2); FFMA2(acc[2][3], a2, bd3);              \
            FFMA2(acc[3][0], a3, bd0); FFMA2(acc[3][1], a3, bd1);              \
            FFMA2(acc[3][2], a3, bd2); FFMA2(acc[3][3], a3, bd3);              \
        }                                                                      \
    }
#define GEMM_MAIN()                                                            \
    LDB(0); STB(0); __syncthreads();                                           \
    _Pragma("unroll 1")                                                        \
    for (int kc = 0; kc < 8; kc++) {                                           \
        if (kc < 7) LDB(kc + 1);                                               \
        CHUNK_COMPUTE(kc, kc & 1);                                             \
        if (kc < 7) { STB((kc + 1) & 1); __syncthreads(); }                    \
    }

#define STAGE_A(SRC, ROWSEL)                                                   \
    {                                                                          \
        int s = tid & 31;                                                      \
        int li = base + s;                                                     \
        int rsel = -1;                                                         \
        if (li < cnt) { int nn = ROWSEL; rsel = nn; }                          \
        _Pragma("unroll")                                                      \
        for (int pass = 0; pass < 16; pass++) {                                \
            int kq = (tid >> 5) + 4 * pass;                                    \
            float4 v = make_float4(0.f, 0.f, 0.f, 0.f);                        \
            if (rsel >= 0) v = __ldg((const float4*)(SRC + rsel * 256 + kq * 4)); \
            Ast[(kq * 4 + 0) * 32 + s] = v.x;                                  \
            Ast[(kq * 4 + 1) * 32 + s] = v.y;                                  \
            Ast[(kq * 4 + 2) * 32 + s] = v.z;                                  \
            Ast[(kq * 4 + 3) * 32 + s] = v.w;                                  \
        }                                                                      \
    }

// Level-3: V1[n, half] = P[p[n],:] @ core3[:,c, half-cols]
__global__ void __launch_bounds__(128) k_gemm3(const float* __restrict__ B) {
    __shared__ float Ast[256 * 32];
    __shared__ float Bs[2 * 32 * 128];
    int tid = threadIdx.x;
    int t = blockIdx.x >> 1, half = blockIdx.x & 1;
    int2 cb = tile_map(g_cnt3, t);
    int c = cb.x, base = cb.y;
    int cnt = (c >= 0) ? g_cnt3[c] : 0;
    TICKET_CLEAN(g_done3, g_cnt3, GRID3);
    if (c < 0) return;

    STAGE_A(g_P, g_p[g_b3[c * NS + li]]);
    __syncthreads();

    int colg = tid & 31, sg = tid >> 5;
    int brow = tid >> 5, bcol = (tid & 31) * 4;
    const float* Bg = B + c * 256 + half * 128;
    float4 nb[8];
    u64 acc[4][4] = {};
    GEMM_MAIN();

#pragma unroll
    for (int p = 0; p < 4; p++) {
        float lo0, lo1, lo2, lo3, hi0, hi1, hi2, hi3;
        UNPACK64(lo0, hi0, acc[p][0]); UNPACK64(lo1, hi1, acc[p][1]);
        UNPACK64(lo2, hi2, acc[p][2]); UNPACK64(lo3, hi3, acc[p][3]);
        int l0 = base + sg * 8 + 2 * p, l1 = l0 + 1;
        int n0 = (l0 < cnt) ? g_b3[c * NS + l0] : -1;
        int n1 = (l1 < cnt) ? g_b3[c * NS + l1] : -1;
        if (n0 >= 0) *(float4*)&g_V1[n0 * 256 + half * 128 + colg * 4] =
            make_float4(lo0, lo1, lo2, lo3);
        if (n1 >= 0) *(float4*)&g_V1[n1 * 256 + half * 128 + colg * 4] =
            make_float4(hi0, hi1, hi2, hi3);
    }
}

// Level-4 + suffix dot: out[n] += (V1[n]@C4[c])[half] . S[q[n]][half]
__global__ void __launch_bounds__(128) k_gemm4(const float* __restrict__ B,
                                               float* __restrict__ out) {
    __shared__ float Ast[256 * 32];
    __shared__ float Bs[2 * 32 * 128];
    int tid = threadIdx.x;
    int t = blockIdx.x >> 1, half = blockIdx.x & 1;
    int2 cb = tile_map(g_cnt4, t);
    int c = cb.x, base = cb.y;
    int cnt = (c >= 0) ? g_cnt4[c] : 0;
    TICKET_CLEAN(g_done4, g_cnt4, GRID4);
    if (c < 0) return;

    STAGE_A(g_V1, g_b4[c * NS + li]);
    __syncthreads();

    int colg = tid & 31, sg = tid >> 5;
    int brow = tid >> 5, bcol = (tid & 31) * 4;
    const float* Bg = B + c * 256 + half * 128;
    float4 nb[8];
    u64 acc[4][4] = {};
    GEMM_MAIN();

    float part[8];
#pragma unroll
    for (int p = 0; p < 4; p++) {
        float lo0, lo1, lo2, lo3, hi0, hi1, hi2, hi3;
        UNPACK64(lo0, hi0, acc[p][0]); UNPACK64(lo1, hi1, acc[p][1]);
        UNPACK64(lo2, hi2, acc[p][2]); UNPACK64(lo3, hi3, acc[p][3]);
        int l0 = base + sg * 8 + 2 * p, l1 = l0 + 1;
        int nn0 = (l0 < cnt) ? g_b4[c * NS + l0] : -1;
        int nn1 = (l1 < cnt) ? g_b4[c * NS + l1] : -1;
        int q0 = (nn0 >= 0) ? g_q[nn0] : 0;
        int q1 = (nn1 >= 0) ? g_q[nn1] : 0;
        float4 s0 = *(const float4*)(g_S + q0 * 256 + half * 128 + colg * 4);
        float4 s1 = *(const float4*)(g_S + q1 * 256 + half * 128 + colg * 4);
        part[2 * p]     = lo0 * s0.x + lo1 * s0.y + lo2 * s0.z + lo3 * s0.w;
        part[2 * p + 1] = hi0 * s1.x + hi1 * s1.y + hi2 * s1.z + hi3 * s1.w;
    }
#pragma unroll
    for (int i = 0; i < 8; i++) {
#pragma unroll
        for (int off = 16; off > 0; off >>= 1)
            part[i] += __shfl_xor_sync(0xffffffffu, part[i], off);
    }
    if (colg == 0) {
        // two halves accumulate into out[n]; a+b == b+a bitwise -> deterministic
#pragma unroll
        for (int i = 0; i < 8; i++) {
            int l = base + sg * 8 + i;
            if (l < cnt) atomicAdd(out + g_b4[c * NS + l], part[i]);
        }
    }
}

// ---------------------------------------------------------------------------
extern "C" void kernel_launch(void* const* d_in, const int* in_sizes, int n_in,
                              void* d_out, int out_size) {
    const float* core0 = (const float*)d_in[0];
    const float* core1 = (const float*)d_in[1];
    const float* core2 = (const float*)d_in[2];
    const float* core3 = (const float*)d_in[3];
    const float* core4 = (const float*)d_in[4];
    const float* core5 = (const float*)d_in[5];
    const float* core6 = (const float*)d_in[6];
    const float* core7 = (const float*)d_in[7];
    const int*   coords = (const int*)d_in[8];
    float* out = (float*)d_out;

    k_setup<<<144, 256>>>(core0, core1, core2, core5, core6, core7, coords, out);
    k_gemm3<<<GRID3, 128>>>(core3);
    k_gemm4<<<GRID4, 128>>>(core4, out);
}